// round 5
// baseline (speedup 1.0000x reference)
#include <cuda_runtime.h>
#include <math.h>

// Problem constants
#define BB 4
#define SS 2048
#define EE 1024
#define HH 8
#define DD 128
#define BS (BB*SS)          // 8192
#define HD (HH*DD)          // 1024
#define NROW_ELEMS ((size_t)BS*HD)   // 8,388,608

// Scratch (device globals; no allocation allowed)
__device__ float g_z[BS*HD];       // z, then reused for hln
__device__ float g_states[BS*HD];  // scan output
__device__ float g_h1[BS*HD];      // gelu output, then scaled in place by scores (becomes g)
__device__ float g_wnb[BS*HD];     // weighted (no bias term)
__device__ float g_scores[BS*HH];
__device__ float g_v[HD];          // v[h,d] = ff_W2[h,d,:] . w_att
__device__ float g_c[HH];          // c[h]   = ff_b2[h,:]  . w_att

// ---------------------------------------------------------------------------
// Kernel 0: precompute v and c
// ---------------------------------------------------------------------------
__global__ __launch_bounds__(256) void precompute_vc(
    const float* __restrict__ ff_W2, const float* __restrict__ ff_b2,
    const float* __restrict__ w_att, float* __restrict__ v, float* __restrict__ c)
{
    int wid = blockIdx.x * 8 + (threadIdx.x >> 5);
    int lane = threadIdx.x & 31;
    if (wid < HD) {
        const float* rowp = ff_W2 + (size_t)wid * EE;
        float s = 0.f;
        for (int e = lane; e < EE; e += 32) s += rowp[e] * w_att[e];
        #pragma unroll
        for (int o = 16; o > 0; o >>= 1) s += __shfl_xor_sync(0xffffffffu, s, o);
        if (lane == 0) v[wid] = s;
    } else if (wid < HD + HH) {
        int h = wid - HD;
        const float* rowp = ff_b2 + (size_t)h * EE;
        float s = 0.f;
        for (int e = lane; e < EE; e += 32) s += rowp[e] * w_att[e];
        #pragma unroll
        for (int o = 16; o > 0; o >>= 1) s += __shfl_xor_sync(0xffffffffu, s, o);
        if (lane == 0) c[h] = s;
    }
}

// ---------------------------------------------------------------------------
// SGEMM: C[M,N] = act(A[M,K] @ B[K,N] + bias), 128x128 tile, BK=8, 256 thr, 8x8
// ACT: 0=none, 1=tanh, 2=exact gelu
// ---------------------------------------------------------------------------
template<int ACT>
__global__ __launch_bounds__(256)
void sgemm128(const float* __restrict__ Ag, const float* __restrict__ Bg,
              float* __restrict__ Cg, const float* __restrict__ biasg,
              int M, int N, int K, int lda, int ldb, int ldc,
              long bsA, long bsB, long bsC, long bsBias)
{
    __shared__ float As[8][128];
    __shared__ float Bs[8][128];

    const float* A = Ag + (size_t)blockIdx.z * bsA;
    const float* B = Bg + (size_t)blockIdx.z * bsB;
    float* C = Cg + (size_t)blockIdx.z * bsC;
    const float* bias = biasg ? (biasg + (size_t)blockIdx.z * bsBias) : nullptr;

    int tid = threadIdx.x;
    int blockRow = blockIdx.y * 128;
    int blockCol = blockIdx.x * 128;

    int aRow  = tid >> 1;
    int aCol4 = (tid & 1) * 4;
    int bRow  = tid >> 5;
    int bCol  = (tid & 31) * 4;

    const float* Aptr = A + (size_t)(blockRow + aRow) * lda + aCol4;
    const float* Bptr = B + (size_t)bRow * ldb + blockCol + bCol;

    int tx = tid & 15, ty = tid >> 4;
    float acc[8][8] = {};

    int numTiles = K >> 3;
    float4 ra = *(const float4*)Aptr;
    float4 rb = *(const float4*)Bptr;

    for (int kt = 0; kt < numTiles; ++kt) {
        As[aCol4 + 0][aRow] = ra.x;
        As[aCol4 + 1][aRow] = ra.y;
        As[aCol4 + 2][aRow] = ra.z;
        As[aCol4 + 3][aRow] = ra.w;
        *(float4*)&Bs[bRow][bCol] = rb;
        __syncthreads();

        if (kt + 1 < numTiles) {
            ra = *(const float4*)(Aptr + (size_t)(kt + 1) * 8);
            rb = *(const float4*)(Bptr + (size_t)(kt + 1) * 8 * ldb);
        }

        #pragma unroll
        for (int k = 0; k < 8; ++k) {
            float af[8], bf[8];
            *(float4*)&af[0] = *(const float4*)&As[k][ty * 8];
            *(float4*)&af[4] = *(const float4*)&As[k][ty * 8 + 4];
            *(float4*)&bf[0] = *(const float4*)&Bs[k][tx * 8];
            *(float4*)&bf[4] = *(const float4*)&Bs[k][tx * 8 + 4];
            #pragma unroll
            for (int i = 0; i < 8; ++i)
                #pragma unroll
                for (int j = 0; j < 8; ++j)
                    acc[i][j] = fmaf(af[i], bf[j], acc[i][j]);
        }
        __syncthreads();
    }

    float bvals[8];
    #pragma unroll
    for (int j = 0; j < 8; ++j)
        bvals[j] = bias ? bias[blockCol + tx * 8 + j] : 0.f;

    #pragma unroll
    for (int i = 0; i < 8; ++i) {
        int row = blockRow + ty * 8 + i;
        float* cptr = C + (size_t)row * ldc + blockCol + tx * 8;
        float vals[8];
        #pragma unroll
        for (int j = 0; j < 8; ++j) {
            float vv = acc[i][j] + bvals[j];
            if (ACT == 1) vv = tanhf(vv);
            else if (ACT == 2) vv = 0.5f * vv * (1.0f + erff(vv * 0.70710678118654752f));
            vals[j] = vv;
        }
        *(float4*)cptr       = *(float4*)&vals[0];
        *(float4*)(cptr + 4) = *(float4*)&vals[4];
    }
}

// ---------------------------------------------------------------------------
// Kernel 2: sequential scan. One warp per (b,h): 32 warps total. State in regs.
// ---------------------------------------------------------------------------
__global__ __launch_bounds__(32)
void scan_kernel(const float* __restrict__ z, float* __restrict__ states,
                 const float* __restrict__ U_h, const float* __restrict__ U_z,
                 const float* __restrict__ b_u, const float* __restrict__ lns_g,
                 const float* __restrict__ lns_b)
{
    int bh = blockIdx.x;            // 0..31
    int b = bh >> 3, hh = bh & 7;
    int lane = threadIdx.x;
    int d0 = lane * 4;

    float uh[4], uz[4], bu[4], gg[4], be[4];
    #pragma unroll
    for (int j = 0; j < 4; ++j) {
        int d = d0 + j;
        uh[j] = U_h[hh * (DD * DD) + d * (DD + 1)];   // diagonal
        uz[j] = U_z[hh * (DD * DD) + d * (DD + 1)];
        bu[j] = b_u[hh * DD + d];
        gg[j] = lns_g[d];
        be[j] = lns_b[d];
    }
    float hp[4] = {0.f, 0.f, 0.f, 0.f};
    const float4* zp = (const float4*)(z + (size_t)b * SS * HD + hh * DD + d0);
    float4* sp = (float4*)(states + (size_t)b * SS * HD + hh * DD + d0);

    float4 znext = zp[0];
    for (int t = 0; t < SS; ++t) {
        float zt[4] = {znext.x, znext.y, znext.z, znext.w};
        if (t + 1 < SS) znext = zp[(size_t)(t + 1) * (HD / 4)];

        float hn[4];
        float sum = 0.f, sq = 0.f;
        #pragma unroll
        for (int j = 0; j < 4; ++j) {
            float a = fmaf(hp[j], uh[j], fmaf(zt[j], uz[j], bu[j]));
            float u = 1.0f / (1.0f + __expf(-a));
            float vv = u * hp[j] + (1.0f - u) * zt[j];
            hn[j] = vv; sum += vv; sq += vv * vv;
        }
        #pragma unroll
        for (int o = 16; o > 0; o >>= 1) {
            sum += __shfl_xor_sync(0xffffffffu, sum, o);
            sq  += __shfl_xor_sync(0xffffffffu, sq, o);
        }
        float mean = sum * (1.f / 128.f);
        float var  = sq * (1.f / 128.f) - mean * mean;
        float rstd = rsqrtf(var + 1e-5f);
        #pragma unroll
        for (int j = 0; j < 4; ++j)
            hp[j] = (hn[j] - mean) * rstd * gg[j] + be[j];
        float4 o4; o4.x = hp[0]; o4.y = hp[1]; o4.z = hp[2]; o4.w = hp[3];
        sp[(size_t)t * (HD / 4)] = o4;
    }
}

// ---------------------------------------------------------------------------
// Kernel 3: shaped = states * os_diag; per-head LN over D -> hln
// One warp per row (b,s,h). 65536 rows.
// ---------------------------------------------------------------------------
__global__ __launch_bounds__(256)
void hln_kernel(const float* __restrict__ states, float* __restrict__ out,
                const float* __restrict__ out_shaper,
                const float* __restrict__ ffg, const float* __restrict__ ffb)
{
    int row = blockIdx.x * 8 + (threadIdx.x >> 5);
    int lane = threadIdx.x & 31;
    int h = row & 7;
    int d0 = lane * 4;

    float4 xv = *(const float4*)(states + (size_t)row * DD + d0);
    float x[4] = {xv.x, xv.y, xv.z, xv.w};
    float sh[4];
    float sum = 0.f, sq = 0.f;
    #pragma unroll
    for (int j = 0; j < 4; ++j) {
        float osd = out_shaper[h * (DD * DD) + (d0 + j) * (DD + 1)];
        float vv = x[j] * osd;
        sh[j] = vv; sum += vv; sq += vv * vv;
    }
    #pragma unroll
    for (int o = 16; o > 0; o >>= 1) {
        sum += __shfl_xor_sync(0xffffffffu, sum, o);
        sq  += __shfl_xor_sync(0xffffffffu, sq, o);
    }
    float mean = sum * (1.f / 128.f);
    float var  = sq * (1.f / 128.f) - mean * mean;
    float rstd = rsqrtf(var + 1e-5f);
    float y[4];
    #pragma unroll
    for (int j = 0; j < 4; ++j)
        y[j] = (sh[j] - mean) * rstd * ffg[h * DD + d0 + j] + ffb[h * DD + d0 + j];
    float4 o4; o4.x = y[0]; o4.y = y[1]; o4.z = y[2]; o4.w = y[3];
    *(float4*)(out + (size_t)row * DD + d0) = o4;
}

// ---------------------------------------------------------------------------
// Kernel 5: logits = h1 . v + c + b_att; softmax over 8 heads; h1 *= score
// One block per (b,s) row. Warp w handles head w.
// ---------------------------------------------------------------------------
__global__ __launch_bounds__(256)
void softmax_scale_kernel(float* __restrict__ h1, float* __restrict__ scores,
                          const float* __restrict__ v, const float* __restrict__ c,
                          const float* __restrict__ b_att)
{
    int row = blockIdx.x;
    int w = threadIdx.x >> 5;
    int lane = threadIdx.x & 31;

    float* base = h1 + (size_t)row * HD + w * DD + lane * 4;
    float4 xv = *(const float4*)base;
    float4 vv = *(const float4*)(v + w * DD + lane * 4);
    float dot = xv.x * vv.x + xv.y * vv.y + xv.z * vv.z + xv.w * vv.w;
    #pragma unroll
    for (int o = 16; o > 0; o >>= 1) dot += __shfl_xor_sync(0xffffffffu, dot, o);

    __shared__ float sl[8];
    if (lane == 0) sl[w] = dot + c[w] + b_att[0];
    __syncthreads();

    float m = sl[0];
    #pragma unroll
    for (int i = 1; i < 8; ++i) m = fmaxf(m, sl[i]);
    float tot = 0.f, ew = 0.f;
    #pragma unroll
    for (int i = 0; i < 8; ++i) {
        float e = expf(sl[i] - m);
        tot += e;
        if (i == w) ew = e;
    }
    float score = ew / tot;
    xv.x *= score; xv.y *= score; xv.z *= score; xv.w *= score;
    *(float4*)base = xv;
    if (lane == 0) scores[row * HH + w] = score;
}

// ---------------------------------------------------------------------------
// Kernel 7: out = LN_E( wnb + scores @ ff_b2 ). One block per (b,s) row.
// ---------------------------------------------------------------------------
__global__ __launch_bounds__(256)
void final_ln_kernel(const float* __restrict__ wnb, const float* __restrict__ scores,
                     const float* __restrict__ ff_b2, const float* __restrict__ lno_g,
                     const float* __restrict__ lno_b, float* __restrict__ out)
{
    int row = blockIdx.x;
    int tid = threadIdx.x;
    int i = tid * 4;

    float s[8];
    #pragma unroll
    for (int h = 0; h < 8; ++h) s[h] = scores[row * HH + h];

    float4 wv = *(const float4*)(wnb + (size_t)row * EE + i);
    float val[4] = {wv.x, wv.y, wv.z, wv.w};
    #pragma unroll
    for (int h = 0; h < 8; ++h) {
        float4 bb = *(const float4*)(ff_b2 + (size_t)h * EE + i);
        val[0] = fmaf(s[h], bb.x, val[0]);
        val[1] = fmaf(s[h], bb.y, val[1]);
        val[2] = fmaf(s[h], bb.z, val[2]);
        val[3] = fmaf(s[h], bb.w, val[3]);
    }

    float ls = val[0] + val[1] + val[2] + val[3];
    float lq = val[0]*val[0] + val[1]*val[1] + val[2]*val[2] + val[3]*val[3];
    #pragma unroll
    for (int o = 16; o > 0; o >>= 1) {
        ls += __shfl_xor_sync(0xffffffffu, ls, o);
        lq += __shfl_xor_sync(0xffffffffu, lq, o);
    }
    __shared__ float s_sum[8], s_sq[8];
    if ((tid & 31) == 0) { s_sum[tid >> 5] = ls; s_sq[tid >> 5] = lq; }
    __syncthreads();
    float S = 0.f, Q = 0.f;
    #pragma unroll
    for (int w = 0; w < 8; ++w) { S += s_sum[w]; Q += s_sq[w]; }

    float mean = S * (1.f / 1024.f);
    float var  = Q * (1.f / 1024.f) - mean * mean;
    float rstd = rsqrtf(var + 1e-5f);

    float4 gv = *(const float4*)(lno_g + i);
    float4 bv = *(const float4*)(lno_b + i);
    float4 o4;
    o4.x = (val[0] - mean) * rstd * gv.x + bv.x;
    o4.y = (val[1] - mean) * rstd * gv.y + bv.y;
    o4.z = (val[2] - mean) * rstd * gv.z + bv.z;
    o4.w = (val[3] - mean) * rstd * gv.w + bv.w;
    *(float4*)(out + (size_t)row * EE + i) = o4;
}

// ---------------------------------------------------------------------------
extern "C" void kernel_launch(void* const* d_in, const int* in_sizes, int n_in,
                              void* d_out, int out_size)
{
    const float* x         = (const float*)d_in[0];
    const float* W_ez      = (const float*)d_in[1];
    const float* b_ez      = (const float*)d_in[2];
    const float* U_h       = (const float*)d_in[3];
    const float* U_z       = (const float*)d_in[4];
    const float* b_u       = (const float*)d_in[5];
    const float* out_shaper= (const float*)d_in[6];
    const float* lns_g     = (const float*)d_in[7];
    const float* lns_b     = (const float*)d_in[8];
    const float* ff_ln_g   = (const float*)d_in[9];
    const float* ff_ln_b   = (const float*)d_in[10];
    const float* ff_W1     = (const float*)d_in[11];
    const float* ff_b1     = (const float*)d_in[12];
    const float* ff_W2     = (const float*)d_in[13];
    const float* ff_b2     = (const float*)d_in[14];
    const float* w_att     = (const float*)d_in[15];
    const float* b_att     = (const float*)d_in[16];
    const float* lno_g     = (const float*)d_in[17];
    const float* lno_b     = (const float*)d_in[18];
    float* out = (float*)d_out;

    float *pz, *pst, *ph1, *pwnb, *psc, *pv, *pc;
    cudaGetSymbolAddress((void**)&pz,  g_z);
    cudaGetSymbolAddress((void**)&pst, g_states);
    cudaGetSymbolAddress((void**)&ph1, g_h1);
    cudaGetSymbolAddress((void**)&pwnb,g_wnb);
    cudaGetSymbolAddress((void**)&psc, g_scores);
    cudaGetSymbolAddress((void**)&pv,  g_v);
    cudaGetSymbolAddress((void**)&pc,  g_c);

    // 0) v = ff_W2 @ w_att, c = ff_b2 @ w_att
    precompute_vc<<<129, 256>>>(ff_W2, ff_b2, w_att, pv, pc);

    // 1) z = tanh(x @ W_ez + b_ez)   [8192,1024]x[1024,1024]
    sgemm128<1><<<dim3(8, 64, 1), 256>>>(x, W_ez, pz, b_ez,
                                         BS, HD, EE, EE, HD, HD, 0, 0, 0, 0);

    // 2) sequential gated scan + per-step LN  -> states
    scan_kernel<<<32, 32>>>(pz, pst, U_h, U_z, b_u, lns_g, lns_b);

    // 3) shaped + per-head LN -> hln (reuse g_z)
    hln_kernel<<<BS * HH / 8, 256>>>(pst, pz, out_shaper, ff_ln_g, ff_ln_b);

    // 4) h1 = gelu(hln @ ff_W1[h] + ff_b1[h])  batched over heads
    sgemm128<2><<<dim3(1, 64, 8), 256>>>(pz, ff_W1, ph1, ff_b1,
                                         BS, DD, DD, HD, DD, HD,
                                         DD, (long)DD * DD, DD, DD);

    // 5) logits -> softmax over heads -> h1 *= score (in place), store scores
    softmax_scale_kernel<<<BS, 256>>>(ph1, psc, pv, pc, b_att);

    // 6) wnb = (s .* h1) @ ff_W2   [8192,1024]x[1024,1024]
    sgemm128<0><<<dim3(8, 64, 1), 256>>>(ph1, ff_W2, pwnb, nullptr,
                                         BS, EE, HD, HD, EE, EE, 0, 0, 0, 0);

    // 7) out = LN_E(wnb + scores @ ff_b2)
    final_ln_kernel<<<BS, 256>>>(pwnb, psc, ff_b2, lno_g, lno_b, out);
}